// round 11
// baseline (speedup 1.0000x reference)
#include <cuda_runtime.h>
#include <math_constants.h>

#define HH 512
#define WW 1024
#define NPIX (HH * WW)      // 524288 = 2^19
#define KNB 15
#define GAMMA_F 0.1f

#define BLOCK 256
#define NBLK  592                     // 148 SMs x 4 CTAs -> all co-resident
#define NTHREADS (NBLK * BLOCK)       // 151552
#define TILE 5
#define NTILE (KNB / TILE)            // 3

// Packed per-pixel data, 16 bytes: (s, nx, ny, nz).
__device__ float4 g_packed[NPIX];
__device__ float  g_partials[NBLK];
__device__ unsigned int g_c1;        // pack-phase arrival counter
__device__ unsigned int g_release;   // pack-phase release flag
__device__ unsigned int g_done;      // loss-phase done counter

// Direction from pixel index (ERP grid), fast intrinsics.
__device__ __forceinline__ void erp_dir(int i, float& dx, float& dy, float& dz) {
    int row = i >> 10;          // W = 1024
    int col = i & 1023;
    float lat = 0.5f * CUDART_PI_F - (row + 0.5f) * (CUDART_PI_F / HH);
    float lon = (col + 0.5f) * (2.0f * CUDART_PI_F / WW) - CUDART_PI_F;
    float sla = __sinf(lat), cla = __cosf(lat);
    float slo = __sinf(lon), clo = __cosf(lon);
    dx = cla * slo;
    dy = sla;
    dz = cla * clo;
}

// ---------------- Fused persistent kernel: pack -> grid barrier -> loss -> reduce ----------------
__global__ void __launch_bounds__(BLOCK, 4) fused_kernel(const float* __restrict__ sig1,
                                                         const float* __restrict__ sig2,
                                                         const float* __restrict__ weights,
                                                         const int* __restrict__ nb,
                                                         float* __restrict__ out) {
    int gtid = blockIdx.x * BLOCK + threadIdx.x;

    // ---- Phase 1: pack {s, nx, ny, nz} (grid-strided, 3-4 px/thread) ----
    for (int i = gtid; i < NPIX; i += NTHREADS) {
        float s  = sig1[i];
        float nx = sig2[i];
        float ny = sig2[NPIX + i];
        float nz = sig2[2 * NPIX + i];
        g_packed[i] = make_float4(s, nx, ny, nz);
    }

    // ---- Grid barrier (all 592 CTAs are co-resident by construction) ----
    __threadfence();          // pack stores visible GPU-wide (L2)
    __syncthreads();          // whole CTA done packing before arrival
    if (threadIdx.x == 0) {
        unsigned prev = atomicAdd(&g_c1, 1u);
        if (prev == NBLK - 1) {
            atomicExch(&g_release, 1u);
        } else {
            while (atomicAdd(&g_release, 0u) == 0u) __nanosleep(64);
        }
    }
    __syncthreads();

    // ---- Phase 2: loss (R5 shape: 15-idx preload, 5-wide gather tiles) ----
    float vsum = 0.0f;
    for (int i = gtid; i < NPIX; i += NTHREADS) {
        // All neighbour indices (independent coalesced loads)
        int idx[KNB];
#pragma unroll
        for (int k = 0; k < KNB; k++)
            idx[k] = __ldcs(&nb[k * NPIX + i]) & (NPIX - 1);

        // Own pixel
        float4 E = __ldg(&g_packed[i]);
        float dix, diy, diz;
        erp_dir(i, dix, diy, diz);
        float nix = E.y, niy = E.z, niz = E.w;
        float pn_i = E.x * (dix * nix + diy * niy + diz * niz);

        float acc1 = 0.0f;
        float acc2 = 0.0f;

#pragma unroll
        for (int t = 0; t < NTILE; t++) {
            // 5 gathers in flight (one LDG.128 each, L1-cached)
            float4 e[TILE];
#pragma unroll
            for (int u = 0; u < TILE; u++)
                e[u] = __ldg(&g_packed[idx[t * TILE + u]]);

            float wv[TILE];
#pragma unroll
            for (int u = 0; u < TILE; u++)
                wv[u] = __ldcs(&weights[(t * TILE + u) * NPIX + i]);

#pragma unroll
            for (int u = 0; u < TILE; u++) {
                float djx, djy, djz;
                erp_dir(idx[t * TILE + u], djx, djy, djz);

                float dotpn = e[u].x * (djx * nix + djy * niy + djz * niz);
                float aux1 = pn_i - dotpn;

                float ddx = nix - e[u].y;
                float ddy = niy - e[u].z;
                float ddz = niz - e[u].w;
                float aux2 = sqrtf(ddx * ddx + ddy * ddy + ddz * ddz);

                float tt = aux1 * wv[u];
                acc1 += tt * tt;
                acc2 += aux2 * wv[u];
            }
        }

        vsum += sqrtf(acc1) + GAMMA_F * acc2;
    }

    // ---- Deterministic block tree-reduce ----
    __shared__ float sm[BLOCK];
    sm[threadIdx.x] = vsum;
    __syncthreads();
#pragma unroll
    for (int s = BLOCK / 2; s > 0; s >>= 1) {
        if (threadIdx.x < s) sm[threadIdx.x] += sm[threadIdx.x + s];
        __syncthreads();
    }

    __shared__ bool amLast;
    if (threadIdx.x == 0) {
        g_partials[blockIdx.x] = sm[0];
        __threadfence();
        unsigned prev = atomicAdd(&g_done, 1u);
        amLast = (prev == NBLK - 1);
    }
    __syncthreads();

    // ---- Last block: final reduce + counter reset for next graph replay ----
    if (amLast) {
        float acc = 0.0f;
        for (int p = threadIdx.x; p < NBLK; p += BLOCK)
            acc += __ldcg(&g_partials[p]);
        sm[threadIdx.x] = acc;
        __syncthreads();
#pragma unroll
        for (int s = BLOCK / 2; s > 0; s >>= 1) {
            if (threadIdx.x < s) sm[threadIdx.x] += sm[threadIdx.x + s];
            __syncthreads();
        }
        if (threadIdx.x == 0) {
            out[0] = sm[0] * (1.0f / (float)NPIX);   // MULTIPLIER = 1.0
            // Reset sync state (every other CTA has passed both sync points)
            g_c1 = 0u;
            g_release = 0u;
            g_done = 0u;
            __threadfence();
        }
    }
}

extern "C" void kernel_launch(void* const* d_in, const int* in_sizes, int n_in,
                              void* d_out, int out_size) {
    const float* sig1    = (const float*)d_in[0];   // N f32
    const float* sig2    = (const float*)d_in[1];   // 3N f32
    const float* weights = (const float*)d_in[2];   // K*N f32
    const int*   nb      = (const int*)d_in[3];     // K*N int32
    float* out = (float*)d_out;

    fused_kernel<<<NBLK, BLOCK>>>(sig1, sig2, weights, nb, out);
}